// round 1
// baseline (speedup 1.0000x reference)
#include <cuda_runtime.h>
#include <cuda_bf16.h>

#define NN 50000
#define NE 600000
#define IN_SZ 128
#define HID 256
#define OUT_SZ 128

// ---------------- scratch (device globals: no runtime allocation) ----------
__device__ float g_agg1[NN * IN_SZ];    // segment_sum(feat[src]) per dst
__device__ float g_agg2[NN * OUT_SZ];   // segment_sum(yl[src]) per dst
__device__ float g_cnt[NN];             // in-degree (float)
__device__ float g_inv[NN];             // 1/max(cnt,1)
__device__ float g_y[NN * HID];         // gemm1 pre-act out; later gemm2 out [yl|yr]
__device__ float g_h1[NN * HID];        // layer-1 activations

// ---------------- zero scratch ---------------------------------------------
__global__ void gs_zero_kernel() {
    int i = blockIdx.x * blockDim.x + threadIdx.x;
    const int n4 = (NN * IN_SZ) / 4;  // 1.6M float4 per agg buffer
    if (i < n4) {
        ((float4*)g_agg1)[i] = make_float4(0.f, 0.f, 0.f, 0.f);
        ((float4*)g_agg2)[i] = make_float4(0.f, 0.f, 0.f, 0.f);
    }
    if (i < NN) g_cnt[i] = 0.f;
}

// ---------------- edge scatter: warp per edge, red.add.v4 -------------------
__global__ void gs_scatter_kernel(const float* __restrict__ X, int xstride,
                                  float* __restrict__ AGG,
                                  const int* __restrict__ ei, int do_count) {
    int t = blockIdx.x * blockDim.x + threadIdx.x;
    int e = t >> 5;
    if (e >= NE) return;
    int lane = t & 31;
    int src = 0, dst = 0;
    if (lane == 0) { src = ei[e]; dst = ei[NE + e]; }
    src = __shfl_sync(0xffffffffu, src, 0);
    dst = __shfl_sync(0xffffffffu, dst, 0);

    const float4 v = *(const float4*)(X + (size_t)src * xstride + lane * 4);
    float* p = AGG + (size_t)dst * 128 + lane * 4;
    asm volatile("red.global.add.v4.f32 [%0], {%1,%2,%3,%4};"
                 :: "l"(p), "f"(v.x), "f"(v.y), "f"(v.z), "f"(v.w) : "memory");
    if (do_count && lane == 0) atomicAdd(&g_cnt[dst], 1.0f);
}

// ---------------- inverse degree -------------------------------------------
__global__ void gs_inv_kernel() {
    int i = blockIdx.x * blockDim.x + threadIdx.x;
    if (i < NN) g_inv[i] = 1.0f / fmaxf(g_cnt[i], 1.0f);
}

// ---------------- GEMM: C[50000,256] = A[50000,256] @ W[256,256]^T (+bias) --
// MODE 1 (layer 1): A[:, 0:128]  = g_agg1 * inv (mean), A[:,128:256] = feat
//                   W[j, 0:128]  = W1l[j],  W[j,128:256] = W1r[j]
// MODE 2 (layer 2): A = g_h1,    W[j] = (j<128 ? W2l[j] : W2r[j-128])
template <int MODE>
__global__ void gs_gemm_kernel(const float* __restrict__ A0,   // agg1 or h1
                               const float* __restrict__ A1,   // feat or null
                               const float* __restrict__ Wa,   // W1l or W2l
                               const float* __restrict__ Wb,   // W1r or W2r
                               const float* __restrict__ bias, // b1 or null
                               float* __restrict__ C) {
    constexpr int BM = 128, BN = 128, BK = 16, TM = 8, TN = 8;
    __shared__ float As[BK][BM + 4];
    __shared__ float Bs[BK][BN];

    const int tid = threadIdx.x;              // 256 threads
    const int m0  = blockIdx.x * BM;
    const int n0  = blockIdx.y * BN;
    const int tm  = tid >> 4;                 // 0..15
    const int tn  = tid & 15;                 // 0..15

    float acc[TM][TN];
    #pragma unroll
    for (int i = 0; i < TM; ++i)
        #pragma unroll
        for (int j = 0; j < TN; ++j) acc[i][j] = 0.f;

    for (int kt = 0; kt < 256 / BK; ++kt) {
        const int k0 = kt * BK;

        // ---- load A tile (BM x BK) into As[k][m] -------------------------
        #pragma unroll
        for (int l = 0; l < 2; ++l) {
            int idx = tid + l * 256;          // 0..511
            int r   = idx >> 2;               // 0..127
            int kq  = (idx & 3) * 4;          // 0,4,8,12
            int row = m0 + r;
            float4 v = make_float4(0.f, 0.f, 0.f, 0.f);
            if (row < NN) {
                if (MODE == 1) {
                    if (k0 < 128) {
                        v = *(const float4*)(A0 + (size_t)row * 128 + k0 + kq);
                        float s = g_inv[row];
                        v.x *= s; v.y *= s; v.z *= s; v.w *= s;
                    } else {
                        v = *(const float4*)(A1 + (size_t)row * 128 + (k0 - 128) + kq);
                    }
                } else {
                    v = *(const float4*)(A0 + (size_t)row * 256 + k0 + kq);
                }
            }
            As[kq + 0][r] = v.x; As[kq + 1][r] = v.y;
            As[kq + 2][r] = v.z; As[kq + 3][r] = v.w;
        }

        // ---- load W tile into Bs[k][n] -----------------------------------
        #pragma unroll
        for (int l = 0; l < 2; ++l) {
            int idx = tid + l * 256;
            int j   = idx >> 2;               // 0..127 (within n-tile)
            int kq  = (idx & 3) * 4;
            int col = n0 + j;                 // global output channel
            const float* wp;
            if (MODE == 1) {
                wp = (k0 < 128) ? (Wa + (size_t)col * 128 + k0 + kq)
                                : (Wb + (size_t)col * 128 + (k0 - 128) + kq);
            } else {
                wp = (col < 128) ? (Wa + (size_t)col * 256 + k0 + kq)
                                 : (Wb + (size_t)(col - 128) * 256 + k0 + kq);
            }
            float4 w = *(const float4*)wp;
            Bs[kq + 0][j] = w.x; Bs[kq + 1][j] = w.y;
            Bs[kq + 2][j] = w.z; Bs[kq + 3][j] = w.w;
        }
        __syncthreads();

        // ---- compute ------------------------------------------------------
        #pragma unroll
        for (int kk = 0; kk < BK; ++kk) {
            float a[TM], b[TN];
            #pragma unroll
            for (int i = 0; i < TM; ++i) a[i] = As[kk][tm * TM + i];
            #pragma unroll
            for (int j = 0; j < TN; ++j) b[j] = Bs[kk][tn * TN + j];
            #pragma unroll
            for (int i = 0; i < TM; ++i)
                #pragma unroll
                for (int j = 0; j < TN; ++j)
                    acc[i][j] = fmaf(a[i], b[j], acc[i][j]);
        }
        __syncthreads();
    }

    // ---- epilogue: optional bias, store --------------------------------
    #pragma unroll
    for (int i = 0; i < TM; ++i) {
        int row = m0 + tm * TM + i;
        if (row >= NN) continue;
        size_t base = (size_t)row * 256 + n0 + tn * TN;
        #pragma unroll
        for (int j = 0; j < TN; j += 4) {
            float4 c;
            c.x = acc[i][j + 0]; c.y = acc[i][j + 1];
            c.z = acc[i][j + 2]; c.w = acc[i][j + 3];
            if (bias) {
                int col = n0 + tn * TN + j;
                c.x += bias[col + 0]; c.y += bias[col + 1];
                c.z += bias[col + 2]; c.w += bias[col + 3];
            }
            *(float4*)(C + base + j) = c;
        }
    }
}

// ---------------- layer-1 epilogue: L2-normalize row, relu ------------------
__global__ void gs_norm_relu_kernel() {
    int t = blockIdx.x * blockDim.x + threadIdx.x;
    int n = t >> 5;
    if (n >= NN) return;
    int lane = t & 31;
    const float* row = g_y + (size_t)n * 256;
    float4 v0 = *(const float4*)(row + lane * 4);
    float4 v1 = *(const float4*)(row + 128 + lane * 4);
    float s = v0.x * v0.x + v0.y * v0.y + v0.z * v0.z + v0.w * v0.w
            + v1.x * v1.x + v1.y * v1.y + v1.z * v1.z + v1.w * v1.w;
    #pragma unroll
    for (int o = 16; o > 0; o >>= 1) s += __shfl_xor_sync(0xffffffffu, s, o);
    float scale = 1.0f / fmaxf(sqrtf(s), 1e-12f);
    float* out = g_h1 + (size_t)n * 256;
    float4 r0, r1;
    r0.x = fmaxf(v0.x * scale, 0.f); r0.y = fmaxf(v0.y * scale, 0.f);
    r0.z = fmaxf(v0.z * scale, 0.f); r0.w = fmaxf(v0.w * scale, 0.f);
    r1.x = fmaxf(v1.x * scale, 0.f); r1.y = fmaxf(v1.y * scale, 0.f);
    r1.z = fmaxf(v1.z * scale, 0.f); r1.w = fmaxf(v1.w * scale, 0.f);
    *(float4*)(out + lane * 4)       = r0;
    *(float4*)(out + 128 + lane * 4) = r1;
}

// ---------------- final: combine, normalize, fc head, softmax ---------------
__global__ void gs_final_kernel(const float* __restrict__ b2,
                                const float* __restrict__ Wfc,
                                const float* __restrict__ bfc,
                                float* __restrict__ out) {
    int t = blockIdx.x * blockDim.x + threadIdx.x;
    int n = t >> 5;
    if (n >= NN) return;
    int lane = t & 31;

    float inv = g_inv[n];
    float4 a = *(const float4*)(g_agg2 + (size_t)n * 128 + lane * 4);
    float4 r = *(const float4*)(g_y + (size_t)n * 256 + 128 + lane * 4); // yr
    float4 bb = *(const float4*)(b2 + lane * 4);
    float4 v;
    v.x = a.x * inv + r.x + bb.x;
    v.y = a.y * inv + r.y + bb.y;
    v.z = a.z * inv + r.z + bb.z;
    v.w = a.w * inv + r.w + bb.w;

    float s = v.x * v.x + v.y * v.y + v.z * v.z + v.w * v.w;
    #pragma unroll
    for (int o = 16; o > 0; o >>= 1) s += __shfl_xor_sync(0xffffffffu, s, o);
    float scale = 1.0f / fmaxf(sqrtf(s), 1e-12f);
    v.x *= scale; v.y *= scale; v.z *= scale; v.w *= scale;

    float4 w0 = *(const float4*)(Wfc + lane * 4);
    float4 w1 = *(const float4*)(Wfc + 128 + lane * 4);
    float l0 = v.x * w0.x + v.y * w0.y + v.z * w0.z + v.w * w0.w;
    float l1 = v.x * w1.x + v.y * w1.y + v.z * w1.z + v.w * w1.w;
    #pragma unroll
    for (int o = 16; o > 0; o >>= 1) {
        l0 += __shfl_xor_sync(0xffffffffu, l0, o);
        l1 += __shfl_xor_sync(0xffffffffu, l1, o);
    }
    if (lane == 0) {
        l0 += bfc[0]; l1 += bfc[1];
        float m  = fmaxf(l0, l1);
        float e0 = expf(l0 - m), e1 = expf(l1 - m);
        float d  = 1.0f / (e0 + e1);
        out[(size_t)n * 2 + 0] = e0 * d;
        out[(size_t)n * 2 + 1] = e1 * d;
    }
}

// ---------------- launch -----------------------------------------------------
extern "C" void kernel_launch(void* const* d_in, const int* in_sizes, int n_in,
                              void* d_out, int out_size) {
    const float* feat = (const float*)d_in[0];
    const int*   ei   = (const int*)d_in[1];
    const float* W1l  = (const float*)d_in[2];
    const float* b1   = (const float*)d_in[3];
    const float* W1r  = (const float*)d_in[4];
    const float* W2l  = (const float*)d_in[5];
    const float* b2   = (const float*)d_in[6];
    const float* W2r  = (const float*)d_in[7];
    const float* Wfc  = (const float*)d_in[8];
    const float* bfc  = (const float*)d_in[9];
    float* out = (float*)d_out;

    // resolve device-global scratch pointers (host-visible addresses)
    float *p_agg1, *p_agg2, *p_y, *p_h1;
    cudaGetSymbolAddress((void**)&p_agg1, g_agg1);
    cudaGetSymbolAddress((void**)&p_agg2, g_agg2);
    cudaGetSymbolAddress((void**)&p_y,    g_y);
    cudaGetSymbolAddress((void**)&p_h1,   g_h1);

    // 1) zero accumulators + degree
    gs_zero_kernel<<<(NN * IN_SZ / 4 + 255) / 256, 256>>>();

    // 2) layer-1 scatter: agg1 += feat[src] per dst; count degrees
    gs_scatter_kernel<<<(NE * 32 + 255) / 256, 256>>>(feat, 128, p_agg1, ei, 1);

    // 3) inverse degree
    gs_inv_kernel<<<(NN + 255) / 256, 256>>>();

    // 4) layer-1 GEMM: y = mean(agg1) @ W1l^T + feat @ W1r^T + b1
    {
        dim3 grid((NN + 127) / 128, 2);
        gs_gemm_kernel<1><<<grid, 256>>>(p_agg1, feat, W1l, W1r, b1, p_y);
    }

    // 5) normalize + relu -> h1
    gs_norm_relu_kernel<<<(NN * 32 + 255) / 256, 256>>>();

    // 6) layer-2 GEMM: y = [h1 @ W2l^T | h1 @ W2r^T]
    {
        dim3 grid((NN + 127) / 128, 2);
        gs_gemm_kernel<2><<<grid, 256>>>(p_h1, nullptr, W2l, W2r, nullptr, p_y);
    }

    // 7) layer-2 scatter: agg2 += yl[src] per dst  (yl = y[:, :128])
    gs_scatter_kernel<<<(NE * 32 + 255) / 256, 256>>>(p_y, 256, p_agg2, ei, 0);

    // 8) final: mean + yr + b2, normalize, fc, softmax
    gs_final_kernel<<<(NN * 32 + 255) / 256, 256>>>(b2, Wfc, bfc, out);
}

// round 2
// speedup vs baseline: 1.7846x; 1.7846x over previous
#include <cuda_runtime.h>
#include <cuda_bf16.h>
#include <cstdint>

#define NN 50000
#define NE 600000
#define IN_SZ 128
#define HID 256
#define OUT_SZ 128

// ---------------- scratch (device globals: no runtime allocation) ----------
__device__ float g_agg1[NN * IN_SZ];
__device__ float g_agg2[NN * OUT_SZ];
__device__ float g_cnt[NN];
__device__ float g_inv[NN];
__device__ float g_y[NN * HID];
__device__ float g_h1[NN * HID];

// ---------------- zero scratch ---------------------------------------------
__global__ void gs_zero_kernel() {
    int i = blockIdx.x * blockDim.x + threadIdx.x;
    const int n4 = (NN * IN_SZ) / 4;
    if (i < n4) {
        ((float4*)g_agg1)[i] = make_float4(0.f, 0.f, 0.f, 0.f);
        ((float4*)g_agg2)[i] = make_float4(0.f, 0.f, 0.f, 0.f);
    }
    if (i < NN) g_cnt[i] = 0.f;
}

// ---------------- edge scatter: warp per edge, red.add.v4 -------------------
__global__ void gs_scatter_kernel(const float* __restrict__ X, int xstride,
                                  float* __restrict__ AGG,
                                  const int* __restrict__ ei, int do_count) {
    int t = blockIdx.x * blockDim.x + threadIdx.x;
    int e = t >> 5;
    if (e >= NE) return;
    int lane = t & 31;
    int src = 0, dst = 0;
    if (lane == 0) { src = ei[e]; dst = ei[NE + e]; }
    src = __shfl_sync(0xffffffffu, src, 0);
    dst = __shfl_sync(0xffffffffu, dst, 0);

    const float4 v = *(const float4*)(X + (size_t)src * xstride + lane * 4);
    float* p = AGG + (size_t)dst * 128 + lane * 4;
    asm volatile("red.global.add.v4.f32 [%0], {%1,%2,%3,%4};"
                 :: "l"(p), "f"(v.x), "f"(v.y), "f"(v.z), "f"(v.w) : "memory");
    if (do_count && lane == 0) atomicAdd(&g_cnt[dst], 1.0f);
}

// ---------------- inverse degree -------------------------------------------
__global__ void gs_inv_kernel() {
    int i = blockIdx.x * blockDim.x + threadIdx.x;
    if (i < NN) g_inv[i] = 1.0f / fmaxf(g_cnt[i], 1.0f);
}

// ---------------- helpers for MMA GEMM --------------------------------------
__device__ __forceinline__ uint32_t smem_u32(const void* p) {
    return (uint32_t)__cvta_generic_to_shared(p);
}

__device__ __forceinline__ void ldm_x4(uint32_t* r, uint32_t addr) {
    asm volatile("ldmatrix.sync.aligned.m8n8.x4.shared.b16 {%0,%1,%2,%3}, [%4];"
                 : "=r"(r[0]), "=r"(r[1]), "=r"(r[2]), "=r"(r[3]) : "r"(addr));
}
__device__ __forceinline__ void ldm_x2(uint32_t* r, uint32_t addr) {
    asm volatile("ldmatrix.sync.aligned.m8n8.x2.shared.b16 {%0,%1}, [%2];"
                 : "=r"(r[0]), "=r"(r[1]) : "r"(addr));
}
__device__ __forceinline__ void mma_bf16(float* c, const uint32_t* a, const uint32_t* b) {
    asm volatile("mma.sync.aligned.m16n8k16.row.col.f32.bf16.bf16.f32 "
                 "{%0,%1,%2,%3}, {%4,%5,%6,%7}, {%8,%9}, {%0,%1,%2,%3};"
                 : "+f"(c[0]), "+f"(c[1]), "+f"(c[2]), "+f"(c[3])
                 : "r"(a[0]), "r"(a[1]), "r"(a[2]), "r"(a[3]), "r"(b[0]), "r"(b[1]));
}

// split fp32 into bf16 hi + lo (hi+lo captures ~16 mantissa bits)
__device__ __forceinline__ void bf16_split(float x, __nv_bfloat16& h, __nv_bfloat16& l) {
    h = __float2bfloat16(x);
    l = __float2bfloat16(x - __bfloat162float(h));
}

// ---------------- GEMM (tensor cores, bf16x3): C = A @ W^T (+bias) ----------
// MODE 1: A[:,0:128]=g_agg1*inv, A[:,128:256]=feat; W rows: [W1l | W1r] concat-K
// MODE 2: A=g_h1; W rows: j<128 ? W2l[j] : W2r[j-128]  (concat-N)
template <int MODE>
__global__ __launch_bounds__(256)
void gs_gemm_mma(const float* __restrict__ A0, const float* __restrict__ A1,
                 const float* __restrict__ Wa, const float* __restrict__ Wb,
                 const float* __restrict__ bias, float* __restrict__ C) {
    constexpr int BM = 128, BN = 128, BK = 32;
    constexpr int STR = BK + 8;  // bf16 elements per smem row (pad 16B)

    __shared__ __nv_bfloat16 Ah[BM * STR], Al[BM * STR];
    __shared__ __nv_bfloat16 Bh[BN * STR], Bl[BN * STR];

    const int tid  = threadIdx.x;
    const int lane = tid & 31;
    const int warp = tid >> 5;     // 8 warps
    const int wm   = warp >> 1;    // 0..3  -> m offset wm*32
    const int wn   = warp & 1;     // 0..1  -> n offset wn*64
    const int m0   = blockIdx.x * BM;
    const int n0   = blockIdx.y * BN;

    float c[2][8][4];
    #pragma unroll
    for (int i = 0; i < 2; ++i)
        #pragma unroll
        for (int j = 0; j < 8; ++j)
            #pragma unroll
            for (int k = 0; k < 4; ++k) c[i][j][k] = 0.f;

    for (int kt = 0; kt < 256 / BK; ++kt) {
        const int k0 = kt * BK;

        // ---- load + split A tile: 128 rows x 32 floats -------------------
        #pragma unroll
        for (int l = 0; l < 4; ++l) {
            int idx = tid + l * 256;          // 0..1023
            int r   = idx >> 3;               // 0..127
            int kq  = (idx & 7) * 4;          // 0..28
            int row = m0 + r;
            float4 v = make_float4(0.f, 0.f, 0.f, 0.f);
            if (row < NN) {
                if (MODE == 1) {
                    if (k0 < 128) {
                        v = *(const float4*)(A0 + (size_t)row * 128 + k0 + kq);
                        float s = g_inv[row];
                        v.x *= s; v.y *= s; v.z *= s; v.w *= s;
                    } else {
                        v = *(const float4*)(A1 + (size_t)row * 128 + (k0 - 128) + kq);
                    }
                } else {
                    v = *(const float4*)(A0 + (size_t)row * 256 + k0 + kq);
                }
            }
            __nv_bfloat16 h0, l0, h1, l1, h2, l2, h3, l3;
            bf16_split(v.x, h0, l0); bf16_split(v.y, h1, l1);
            bf16_split(v.z, h2, l2); bf16_split(v.w, h3, l3);
            __nv_bfloat162* ph = (__nv_bfloat162*)(Ah + r * STR + kq);
            __nv_bfloat162* pl = (__nv_bfloat162*)(Al + r * STR + kq);
            ph[0] = __nv_bfloat162(h0, h1); ph[1] = __nv_bfloat162(h2, h3);
            pl[0] = __nv_bfloat162(l0, l1); pl[1] = __nv_bfloat162(l2, l3);
        }

        // ---- load + split B tile: 128 n-rows x 32 k-floats ---------------
        #pragma unroll
        for (int l = 0; l < 4; ++l) {
            int idx = tid + l * 256;
            int j   = idx >> 3;               // 0..127 within n-tile
            int kq  = (idx & 7) * 4;
            int col = n0 + j;
            const float* wp;
            if (MODE == 1) {
                wp = (k0 < 128) ? (Wa + (size_t)col * 128 + k0 + kq)
                                : (Wb + (size_t)col * 128 + (k0 - 128) + kq);
            } else {
                wp = (col < 128) ? (Wa + (size_t)col * 256 + k0 + kq)
                                 : (Wb + (size_t)(col - 128) * 256 + k0 + kq);
            }
            float4 v = *(const float4*)wp;
            __nv_bfloat16 h0, l0, h1, l1, h2, l2, h3, l3;
            bf16_split(v.x, h0, l0); bf16_split(v.y, h1, l1);
            bf16_split(v.z, h2, l2); bf16_split(v.w, h3, l3);
            __nv_bfloat162* ph = (__nv_bfloat162*)(Bh + j * STR + kq);
            __nv_bfloat162* pl = (__nv_bfloat162*)(Bl + j * STR + kq);
            ph[0] = __nv_bfloat162(h0, h1); ph[1] = __nv_bfloat162(h2, h3);
            pl[0] = __nv_bfloat162(l0, l1); pl[1] = __nv_bfloat162(l2, l3);
        }
        __syncthreads();

        // ---- compute: 2 k16-steps, 3 MMA passes (hh, hl, lh) -------------
        #pragma unroll
        for (int ks = 0; ks < 2; ++ks) {
            uint32_t ah[2][4], al[2][4];
            #pragma unroll
            for (int mi = 0; mi < 2; ++mi) {
                int r  = wm * 32 + mi * 16 + (lane & 15);
                int cc = ks * 16 + (lane >> 4) * 8;
                ldm_x4(ah[mi], smem_u32(Ah + r * STR + cc));
                ldm_x4(al[mi], smem_u32(Al + r * STR + cc));
            }
            uint32_t bh[8][2], bl[8][2];
            #pragma unroll
            for (int ni = 0; ni < 8; ++ni) {
                int r  = wn * 64 + ni * 8 + (lane & 7);
                int cc = ks * 16 + ((lane >> 3) & 1) * 8;
                ldm_x2(bh[ni], smem_u32(Bh + r * STR + cc));
                ldm_x2(bl[ni], smem_u32(Bl + r * STR + cc));
            }
            #pragma unroll
            for (int mi = 0; mi < 2; ++mi)
                #pragma unroll
                for (int ni = 0; ni < 8; ++ni) {
                    mma_bf16(c[mi][ni], ah[mi], bh[ni]);
                    mma_bf16(c[mi][ni], ah[mi], bl[ni]);
                    mma_bf16(c[mi][ni], al[mi], bh[ni]);
                }
        }
        __syncthreads();
    }

    // ---- epilogue ----------------------------------------------------------
    #pragma unroll
    for (int mi = 0; mi < 2; ++mi) {
        int row = m0 + wm * 32 + mi * 16 + (lane >> 2);
        #pragma unroll
        for (int ni = 0; ni < 8; ++ni) {
            int col = n0 + wn * 64 + ni * 8 + (lane & 3) * 2;
            float2 v0 = make_float2(c[mi][ni][0], c[mi][ni][1]);
            float2 v1 = make_float2(c[mi][ni][2], c[mi][ni][3]);
            if (MODE == 1) {
                v0.x += bias[col]; v0.y += bias[col + 1];
                v1.x += bias[col]; v1.y += bias[col + 1];
            }
            if (row < NN)     *(float2*)(C + (size_t)row * 256 + col)       = v0;
            if (row + 8 < NN) *(float2*)(C + (size_t)(row + 8) * 256 + col) = v1;
        }
    }
}

// ---------------- layer-1 epilogue: L2-normalize row, relu ------------------
__global__ void gs_norm_relu_kernel() {
    int t = blockIdx.x * blockDim.x + threadIdx.x;
    int n = t >> 5;
    if (n >= NN) return;
    int lane = t & 31;
    const float* row = g_y + (size_t)n * 256;
    float4 v0 = *(const float4*)(row + lane * 4);
    float4 v1 = *(const float4*)(row + 128 + lane * 4);
    float s = v0.x * v0.x + v0.y * v0.y + v0.z * v0.z + v0.w * v0.w
            + v1.x * v1.x + v1.y * v1.y + v1.z * v1.z + v1.w * v1.w;
    #pragma unroll
    for (int o = 16; o > 0; o >>= 1) s += __shfl_xor_sync(0xffffffffu, s, o);
    float scale = 1.0f / fmaxf(sqrtf(s), 1e-12f);
    float* out = g_h1 + (size_t)n * 256;
    float4 r0, r1;
    r0.x = fmaxf(v0.x * scale, 0.f); r0.y = fmaxf(v0.y * scale, 0.f);
    r0.z = fmaxf(v0.z * scale, 0.f); r0.w = fmaxf(v0.w * scale, 0.f);
    r1.x = fmaxf(v1.x * scale, 0.f); r1.y = fmaxf(v1.y * scale, 0.f);
    r1.z = fmaxf(v1.z * scale, 0.f); r1.w = fmaxf(v1.w * scale, 0.f);
    *(float4*)(out + lane * 4)       = r0;
    *(float4*)(out + 128 + lane * 4) = r1;
}

// ---------------- final: combine, normalize, fc head, softmax ---------------
__global__ void gs_final_kernel(const float* __restrict__ b2,
                                const float* __restrict__ Wfc,
                                const float* __restrict__ bfc,
                                float* __restrict__ out) {
    int t = blockIdx.x * blockDim.x + threadIdx.x;
    int n = t >> 5;
    if (n >= NN) return;
    int lane = t & 31;

    float inv = g_inv[n];
    float4 a = *(const float4*)(g_agg2 + (size_t)n * 128 + lane * 4);
    float4 r = *(const float4*)(g_y + (size_t)n * 256 + 128 + lane * 4); // yr
    float4 bb = *(const float4*)(b2 + lane * 4);
    float4 v;
    v.x = a.x * inv + r.x + bb.x;
    v.y = a.y * inv + r.y + bb.y;
    v.z = a.z * inv + r.z + bb.z;
    v.w = a.w * inv + r.w + bb.w;

    float s = v.x * v.x + v.y * v.y + v.z * v.z + v.w * v.w;
    #pragma unroll
    for (int o = 16; o > 0; o >>= 1) s += __shfl_xor_sync(0xffffffffu, s, o);
    float scale = 1.0f / fmaxf(sqrtf(s), 1e-12f);
    v.x *= scale; v.y *= scale; v.z *= scale; v.w *= scale;

    float4 w0 = *(const float4*)(Wfc + lane * 4);
    float4 w1 = *(const float4*)(Wfc + 128 + lane * 4);
    float l0 = v.x * w0.x + v.y * w0.y + v.z * w0.z + v.w * w0.w;
    float l1 = v.x * w1.x + v.y * w1.y + v.z * w1.z + v.w * w1.w;
    #pragma unroll
    for (int o = 16; o > 0; o >>= 1) {
        l0 += __shfl_xor_sync(0xffffffffu, l0, o);
        l1 += __shfl_xor_sync(0xffffffffu, l1, o);
    }
    if (lane == 0) {
        l0 += bfc[0]; l1 += bfc[1];
        float m  = fmaxf(l0, l1);
        float e0 = expf(l0 - m), e1 = expf(l1 - m);
        float d  = 1.0f / (e0 + e1);
        out[(size_t)n * 2 + 0] = e0 * d;
        out[(size_t)n * 2 + 1] = e1 * d;
    }
}

// ---------------- launch -----------------------------------------------------
extern "C" void kernel_launch(void* const* d_in, const int* in_sizes, int n_in,
                              void* d_out, int out_size) {
    const float* feat = (const float*)d_in[0];
    const int*   ei   = (const int*)d_in[1];
    const float* W1l  = (const float*)d_in[2];
    const float* b1   = (const float*)d_in[3];
    const float* W1r  = (const float*)d_in[4];
    const float* W2l  = (const float*)d_in[5];
    const float* b2   = (const float*)d_in[6];
    const float* W2r  = (const float*)d_in[7];
    const float* Wfc  = (const float*)d_in[8];
    const float* bfc  = (const float*)d_in[9];
    float* out = (float*)d_out;

    float *p_agg1, *p_agg2, *p_y, *p_h1;
    cudaGetSymbolAddress((void**)&p_agg1, g_agg1);
    cudaGetSymbolAddress((void**)&p_agg2, g_agg2);
    cudaGetSymbolAddress((void**)&p_y,    g_y);
    cudaGetSymbolAddress((void**)&p_h1,   g_h1);

    gs_zero_kernel<<<(NN * IN_SZ / 4 + 255) / 256, 256>>>();

    gs_scatter_kernel<<<(NE * 32 + 255) / 256, 256>>>(feat, 128, p_agg1, ei, 1);

    gs_inv_kernel<<<(NN + 255) / 256, 256>>>();

    {
        dim3 grid((NN + 127) / 128, 2);
        gs_gemm_mma<1><<<grid, 256>>>(p_agg1, feat, W1l, W1r, b1, p_y);
    }

    gs_norm_relu_kernel<<<(NN * 32 + 255) / 256, 256>>>();

    {
        dim3 grid((NN + 127) / 128, 2);
        gs_gemm_mma<2><<<grid, 256>>>(p_h1, nullptr, W2l, W2r, nullptr, p_y);
    }

    gs_scatter_kernel<<<(NE * 32 + 255) / 256, 256>>>(p_y, 256, p_agg2, ei, 0);

    gs_final_kernel<<<(NN * 32 + 255) / 256, 256>>>(b2, Wfc, bfc, out);
}

// round 3
// speedup vs baseline: 2.5612x; 1.4352x over previous
#include <cuda_runtime.h>
#include <cuda_bf16.h>
#include <cstdint>

#define NN 50000
#define NE 600000
#define NPAD 50176   // NN padded past grid coverage (50048); pad rows stay zero

// ---------------- device-global scratch ------------------------------------
__device__ int   g_deg[NN];
__device__ int   g_off[NN];
__device__ int   g_pos[NN];
__device__ int   g_bsum[64];
__device__ int   g_esrc[NE];
__device__ float g_inv[NN];
__device__ __nv_bfloat16 g_ah[NPAD * 256];
__device__ __nv_bfloat16 g_al[NPAD * 256];
__device__ __nv_bfloat16 g_wh1[256 * 256], g_wl1[256 * 256];
__device__ __nv_bfloat16 g_wh2[256 * 256], g_wl2[256 * 256];
__device__ float g_y[NN * 256];
__device__ float g_m2[NN * 128];

// ---------------- small helpers --------------------------------------------
__device__ __forceinline__ uint32_t smem_u32(const void* p) {
    return (uint32_t)__cvta_generic_to_shared(p);
}
__device__ __forceinline__ void cp16(uint32_t dst, const void* src) {
    asm volatile("cp.async.cg.shared.global [%0], [%1], 16;" :: "r"(dst), "l"(src));
}
__device__ __forceinline__ void cp_commit() {
    asm volatile("cp.async.commit_group;");
}
template <int N> __device__ __forceinline__ void cp_wait() {
    asm volatile("cp.async.wait_group %0;" :: "n"(N));
}
__device__ __forceinline__ void ldm_x4(uint32_t* r, uint32_t addr) {
    asm volatile("ldmatrix.sync.aligned.m8n8.x4.shared.b16 {%0,%1,%2,%3}, [%4];"
                 : "=r"(r[0]), "=r"(r[1]), "=r"(r[2]), "=r"(r[3]) : "r"(addr));
}
__device__ __forceinline__ void mma_bf16(float* c, const uint32_t* a, const uint32_t* b) {
    asm volatile("mma.sync.aligned.m16n8k16.row.col.f32.bf16.bf16.f32 "
                 "{%0,%1,%2,%3}, {%4,%5,%6,%7}, {%8,%9}, {%0,%1,%2,%3};"
                 : "+f"(c[0]), "+f"(c[1]), "+f"(c[2]), "+f"(c[3])
                 : "r"(a[0]), "r"(a[1]), "r"(a[2]), "r"(a[3]), "r"(b[0]), "r"(b[1]));
}
__device__ __forceinline__ void bf16_split(float x, __nv_bfloat16& h, __nv_bfloat16& l) {
    h = __float2bfloat16(x);
    l = __float2bfloat16(x - __bfloat162float(h));
}

// ---------------- CSR build --------------------------------------------------
__global__ void gs_zero_deg() {
    int i = blockIdx.x * blockDim.x + threadIdx.x;
    if (i < NN) g_deg[i] = 0;
}
__global__ void gs_hist(const int* __restrict__ ei) {
    int e = blockIdx.x * blockDim.x + threadIdx.x;
    if (e < NE) atomicAdd(&g_deg[ei[NE + e]], 1);
}
__global__ void gs_scanA() {  // 49 blocks x 1024: block-local exclusive scan
    __shared__ int sh[1024];
    int tid = threadIdx.x;
    int n = blockIdx.x * 1024 + tid;
    int v = (n < NN) ? g_deg[n] : 0;
    sh[tid] = v;
    __syncthreads();
    #pragma unroll
    for (int o = 1; o < 1024; o <<= 1) {
        int t = (tid >= o) ? sh[tid - o] : 0;
        __syncthreads();
        sh[tid] += t;
        __syncthreads();
    }
    if (n < NN) g_off[n] = sh[tid] - v;
    if (tid == 1023) g_bsum[blockIdx.x] = sh[tid];
}
__global__ void gs_scanB() {  // 1 block, 64 threads: exclusive scan of 49 sums
    __shared__ int sh[64];
    int tid = threadIdx.x;
    int v = (tid < 49) ? g_bsum[tid] : 0;
    sh[tid] = v;
    __syncthreads();
    #pragma unroll
    for (int o = 1; o < 64; o <<= 1) {
        int t = (tid >= o) ? sh[tid - o] : 0;
        __syncthreads();
        sh[tid] += t;
        __syncthreads();
    }
    if (tid < 49) g_bsum[tid] = sh[tid] - v;
}
__global__ void gs_scanC() {
    int n = blockIdx.x * blockDim.x + threadIdx.x;
    if (n < NN) {
        int o = g_off[n] + g_bsum[n >> 10];
        g_off[n] = o;
        g_pos[n] = o;
    }
}
__global__ void gs_fill(const int* __restrict__ ei) {
    int e = blockIdx.x * blockDim.x + threadIdx.x;
    if (e >= NE) return;
    int s = ei[e], d = ei[NE + e];
    int p = atomicAdd(&g_pos[d], 1);
    g_esrc[p] = s;
}

// ---------------- gather 1: mean(feat[nbrs]) + own feat -> split bf16 A ------
__global__ void gs_gather1(const float* __restrict__ feat) {
    int t = blockIdx.x * blockDim.x + threadIdx.x;
    int n = t >> 5;
    if (n >= NN) return;
    int lane = t & 31;
    int start = g_off[n], deg = g_deg[n];

    float4 acc = make_float4(0.f, 0.f, 0.f, 0.f);
    int i = 0;
    for (; i + 2 <= deg; i += 2) {
        int s0 = g_esrc[start + i];
        int s1 = g_esrc[start + i + 1];
        float4 v0 = *(const float4*)(feat + (size_t)s0 * 128 + lane * 4);
        float4 v1 = *(const float4*)(feat + (size_t)s1 * 128 + lane * 4);
        acc.x += v0.x + v1.x; acc.y += v0.y + v1.y;
        acc.z += v0.z + v1.z; acc.w += v0.w + v1.w;
    }
    if (i < deg) {
        int s0 = g_esrc[start + i];
        float4 v0 = *(const float4*)(feat + (size_t)s0 * 128 + lane * 4);
        acc.x += v0.x; acc.y += v0.y; acc.z += v0.z; acc.w += v0.w;
    }
    float inv = 1.0f / fmaxf((float)deg, 1.0f);
    if (lane == 0) g_inv[n] = inv;
    acc.x *= inv; acc.y *= inv; acc.z *= inv; acc.w *= inv;

    __nv_bfloat16 h0, l0, h1, l1, h2, l2, h3, l3;
    bf16_split(acc.x, h0, l0); bf16_split(acc.y, h1, l1);
    bf16_split(acc.z, h2, l2); bf16_split(acc.w, h3, l3);
    size_t base = (size_t)n * 256 + lane * 4;
    ((__nv_bfloat162*)(g_ah + base))[0] = __nv_bfloat162(h0, h1);
    ((__nv_bfloat162*)(g_ah + base))[1] = __nv_bfloat162(h2, h3);
    ((__nv_bfloat162*)(g_al + base))[0] = __nv_bfloat162(l0, l1);
    ((__nv_bfloat162*)(g_al + base))[1] = __nv_bfloat162(l2, l3);

    float4 f = *(const float4*)(feat + (size_t)n * 128 + lane * 4);
    bf16_split(f.x, h0, l0); bf16_split(f.y, h1, l1);
    bf16_split(f.z, h2, l2); bf16_split(f.w, h3, l3);
    size_t base2 = (size_t)n * 256 + 128 + lane * 4;
    ((__nv_bfloat162*)(g_ah + base2))[0] = __nv_bfloat162(h0, h1);
    ((__nv_bfloat162*)(g_ah + base2))[1] = __nv_bfloat162(h2, h3);
    ((__nv_bfloat162*)(g_al + base2))[0] = __nv_bfloat162(l0, l1);
    ((__nv_bfloat162*)(g_al + base2))[1] = __nv_bfloat162(l2, l3);
}

// ---------------- weight split: build concat layouts, bf16 hi/lo -------------
__global__ void gs_wsplit(const float* __restrict__ W1l, const float* __restrict__ W1r,
                          const float* __restrict__ W2l, const float* __restrict__ W2r) {
    int i = blockIdx.x * blockDim.x + threadIdx.x;
    if (i < 65536) {
        int n = i >> 8, k = i & 255;
        float w = (k < 128) ? W1l[n * 128 + k] : W1r[n * 128 + (k - 128)];
        __nv_bfloat16 h, l;
        bf16_split(w, h, l);
        g_wh1[i] = h; g_wl1[i] = l;
    } else if (i < 131072) {
        int j = i - 65536;
        int n = j >> 8, k = j & 255;
        float w = (n < 128) ? W2l[n * 256 + k] : W2r[(n - 128) * 256 + k];
        __nv_bfloat16 h, l;
        bf16_split(w, h, l);
        g_wh2[j] = h; g_wl2[j] = l;
    }
}

// ---------------- pipelined bf16x3 GEMM: C[NN,256] = A @ W^T (+bias) --------
// A: g_ah/g_al [NPAD,256]; W: [256,256] (n-major). MODE 1 adds bias.
template <int MODE>
__global__ __launch_bounds__(256, 2)
void gs_gemm_pipe(const __nv_bfloat16* __restrict__ Wh,
                  const __nv_bfloat16* __restrict__ Wl,
                  const float* __restrict__ bias,
                  float* __restrict__ C) {
    constexpr int STR = 40;           // bf16 per smem row (32 + 8 pad)
    constexpr int TSZ = 128 * STR;    // elems per tile
    extern __shared__ __nv_bfloat16 sm[];

    const int tid  = threadIdx.x;
    const int lane = tid & 31;
    const int warp = tid >> 5;
    const int wm   = warp >> 1;       // 0..3 -> m offset wm*32
    const int wn   = warp & 1;        // 0..1 -> n offset wn*64
    const int m0   = blockIdx.x * 128;
    const int n0   = blockIdx.y * 128;

    float c[2][8][4];
    #pragma unroll
    for (int a = 0; a < 2; ++a)
        #pragma unroll
        for (int b = 0; b < 8; ++b)
            #pragma unroll
            for (int k = 0; k < 4; ++k) c[a][b][k] = 0.f;

    // ---- stage loader ------------------------------------------------------
    auto issue_load = [&](int kt, int st) {
        const int k0 = kt * 32;
        __nv_bfloat16* base = sm + st * 4 * TSZ;
        #pragma unroll
        for (int l = 0; l < 2; ++l) {
            int idx = tid + l * 256;   // 0..511
            int r   = idx >> 2;        // 0..127
            int cq  = (idx & 3) * 8;   // bf16 col offset 0,8,16,24
            uint32_t ds = smem_u32(base + r * STR + cq);
            cp16(ds,             g_ah + (size_t)(m0 + r) * 256 + k0 + cq);
            cp16(ds + TSZ * 2,   g_al + (size_t)(m0 + r) * 256 + k0 + cq);
            cp16(ds + TSZ * 4,   Wh   + (size_t)(n0 + r) * 256 + k0 + cq);
            cp16(ds + TSZ * 6,   Wl   + (size_t)(n0 + r) * 256 + k0 + cq);
        }
        cp_commit();
    };

    issue_load(0, 0);

    for (int kt = 0; kt < 8; ++kt) {
        const int st = kt & 1;
        if (kt + 1 < 8) { issue_load(kt + 1, st ^ 1); cp_wait<1>(); }
        else            { cp_wait<0>(); }
        __syncthreads();

        const __nv_bfloat16* Ahs = sm + st * 4 * TSZ;
        const __nv_bfloat16* Als = Ahs + TSZ;
        const __nv_bfloat16* Bhs = Ahs + 2 * TSZ;
        const __nv_bfloat16* Bls = Ahs + 3 * TSZ;

        #pragma unroll
        for (int ks = 0; ks < 2; ++ks) {
            uint32_t ah[2][4], al[2][4];
            #pragma unroll
            for (int mi = 0; mi < 2; ++mi) {
                int r  = wm * 32 + mi * 16 + (lane & 15);
                int cc = ks * 16 + (lane >> 4) * 8;
                ldm_x4(ah[mi], smem_u32(Ahs + r * STR + cc));
                ldm_x4(al[mi], smem_u32(Als + r * STR + cc));
            }
            // B fragments: x4 per pair of n8 tiles
            int mq = lane >> 3, ri = lane & 7;
            #pragma unroll
            for (int nip = 0; nip < 4; ++nip) {
                int row = wn * 64 + nip * 16 + (mq >> 1) * 8 + ri;
                int col = ks * 16 + (mq & 1) * 8;
                uint32_t bh4[4], bl4[4];
                ldm_x4(bh4, smem_u32(Bhs + row * STR + col));
                ldm_x4(bl4, smem_u32(Bls + row * STR + col));
                #pragma unroll
                for (int mi = 0; mi < 2; ++mi) {
                    mma_bf16(c[mi][2 * nip + 0], ah[mi], &bh4[0]);
                    mma_bf16(c[mi][2 * nip + 0], ah[mi], &bl4[0]);
                    mma_bf16(c[mi][2 * nip + 0], al[mi], &bh4[0]);
                    mma_bf16(c[mi][2 * nip + 1], ah[mi], &bh4[2]);
                    mma_bf16(c[mi][2 * nip + 1], ah[mi], &bl4[2]);
                    mma_bf16(c[mi][2 * nip + 1], al[mi], &bh4[2]);
                }
            }
        }
        __syncthreads();
    }

    // ---- epilogue ------------------------------------------------------------
    #pragma unroll
    for (int mi = 0; mi < 2; ++mi) {
        int row = m0 + wm * 32 + mi * 16 + (lane >> 2);
        #pragma unroll
        for (int ni = 0; ni < 8; ++ni) {
            int col = n0 + wn * 64 + ni * 8 + (lane & 3) * 2;
            float2 v0 = make_float2(c[mi][ni][0], c[mi][ni][1]);
            float2 v1 = make_float2(c[mi][ni][2], c[mi][ni][3]);
            if (MODE == 1) {
                float b0 = bias[col], b1 = bias[col + 1];
                v0.x += b0; v0.y += b1;
                v1.x += b0; v1.y += b1;
            }
            if (row < NN)     *(float2*)(C + (size_t)row * 256 + col)       = v0;
            if (row + 8 < NN) *(float2*)(C + (size_t)(row + 8) * 256 + col) = v1;
        }
    }
}

// ---------------- layer-1 epilogue: normalize + relu -> split bf16 ----------
__global__ void gs_norm_relu_split() {
    int t = blockIdx.x * blockDim.x + threadIdx.x;
    int n = t >> 5;
    if (n >= NN) return;
    int lane = t & 31;
    const float* row = g_y + (size_t)n * 256;
    float4 v0 = *(const float4*)(row + lane * 4);
    float4 v1 = *(const float4*)(row + 128 + lane * 4);
    float s = v0.x * v0.x + v0.y * v0.y + v0.z * v0.z + v0.w * v0.w
            + v1.x * v1.x + v1.y * v1.y + v1.z * v1.z + v1.w * v1.w;
    #pragma unroll
    for (int o = 16; o > 0; o >>= 1) s += __shfl_xor_sync(0xffffffffu, s, o);
    float scale = 1.0f / fmaxf(sqrtf(s), 1e-12f);

    float r0 = fmaxf(v0.x * scale, 0.f), r1 = fmaxf(v0.y * scale, 0.f);
    float r2 = fmaxf(v0.z * scale, 0.f), r3 = fmaxf(v0.w * scale, 0.f);
    float r4 = fmaxf(v1.x * scale, 0.f), r5 = fmaxf(v1.y * scale, 0.f);
    float r6 = fmaxf(v1.z * scale, 0.f), r7 = fmaxf(v1.w * scale, 0.f);

    __nv_bfloat16 h0, l0, h1, l1, h2, l2, h3, l3;
    size_t base = (size_t)n * 256 + lane * 4;
    bf16_split(r0, h0, l0); bf16_split(r1, h1, l1);
    bf16_split(r2, h2, l2); bf16_split(r3, h3, l3);
    ((__nv_bfloat162*)(g_ah + base))[0] = __nv_bfloat162(h0, h1);
    ((__nv_bfloat162*)(g_ah + base))[1] = __nv_bfloat162(h2, h3);
    ((__nv_bfloat162*)(g_al + base))[0] = __nv_bfloat162(l0, l1);
    ((__nv_bfloat162*)(g_al + base))[1] = __nv_bfloat162(l2, l3);

    size_t base2 = base + 128;
    bf16_split(r4, h0, l0); bf16_split(r5, h1, l1);
    bf16_split(r6, h2, l2); bf16_split(r7, h3, l3);
    ((__nv_bfloat162*)(g_ah + base2))[0] = __nv_bfloat162(h0, h1);
    ((__nv_bfloat162*)(g_ah + base2))[1] = __nv_bfloat162(h2, h3);
    ((__nv_bfloat162*)(g_al + base2))[0] = __nv_bfloat162(l0, l1);
    ((__nv_bfloat162*)(g_al + base2))[1] = __nv_bfloat162(l2, l3);
}

// ---------------- gather 2: mean(yl[nbrs]) -> g_m2 ---------------------------
__global__ void gs_gather2() {
    int t = blockIdx.x * blockDim.x + threadIdx.x;
    int n = t >> 5;
    if (n >= NN) return;
    int lane = t & 31;
    int start = g_off[n], deg = g_deg[n];

    float4 acc = make_float4(0.f, 0.f, 0.f, 0.f);
    int i = 0;
    for (; i + 2 <= deg; i += 2) {
        int s0 = g_esrc[start + i];
        int s1 = g_esrc[start + i + 1];
        float4 v0 = *(const float4*)(g_y + (size_t)s0 * 256 + lane * 4);
        float4 v1 = *(const float4*)(g_y + (size_t)s1 * 256 + lane * 4);
        acc.x += v0.x + v1.x; acc.y += v0.y + v1.y;
        acc.z += v0.z + v1.z; acc.w += v0.w + v1.w;
    }
    if (i < deg) {
        int s0 = g_esrc[start + i];
        float4 v0 = *(const float4*)(g_y + (size_t)s0 * 256 + lane * 4);
        acc.x += v0.x; acc.y += v0.y; acc.z += v0.z; acc.w += v0.w;
    }
    float inv = g_inv[n];
    acc.x *= inv; acc.y *= inv; acc.z *= inv; acc.w *= inv;
    *(float4*)(g_m2 + (size_t)n * 128 + lane * 4) = acc;
}

// ---------------- final: combine, normalize, fc head, softmax ---------------
__global__ void gs_final_kernel(const float* __restrict__ b2,
                                const float* __restrict__ Wfc,
                                const float* __restrict__ bfc,
                                float* __restrict__ out) {
    int t = blockIdx.x * blockDim.x + threadIdx.x;
    int n = t >> 5;
    if (n >= NN) return;
    int lane = t & 31;

    float4 a = *(const float4*)(g_m2 + (size_t)n * 128 + lane * 4);
    float4 r = *(const float4*)(g_y + (size_t)n * 256 + 128 + lane * 4); // yr
    float4 bb = *(const float4*)(b2 + lane * 4);
    float4 v;
    v.x = a.x + r.x + bb.x;
    v.y = a.y + r.y + bb.y;
    v.z = a.z + r.z + bb.z;
    v.w = a.w + r.w + bb.w;

    float s = v.x * v.x + v.y * v.y + v.z * v.z + v.w * v.w;
    #pragma unroll
    for (int o = 16; o > 0; o >>= 1) s += __shfl_xor_sync(0xffffffffu, s, o);
    float scale = 1.0f / fmaxf(sqrtf(s), 1e-12f);
    v.x *= scale; v.y *= scale; v.z *= scale; v.w *= scale;

    float4 w0 = *(const float4*)(Wfc + lane * 4);
    float4 w1 = *(const float4*)(Wfc + 128 + lane * 4);
    float l0 = v.x * w0.x + v.y * w0.y + v.z * w0.z + v.w * w0.w;
    float l1 = v.x * w1.x + v.y * w1.y + v.z * w1.z + v.w * w1.w;
    #pragma unroll
    for (int o = 16; o > 0; o >>= 1) {
        l0 += __shfl_xor_sync(0xffffffffu, l0, o);
        l1 += __shfl_xor_sync(0xffffffffu, l1, o);
    }
    if (lane == 0) {
        l0 += bfc[0]; l1 += bfc[1];
        float m  = fmaxf(l0, l1);
        float e0 = expf(l0 - m), e1 = expf(l1 - m);
        float d  = 1.0f / (e0 + e1);
        out[(size_t)n * 2 + 0] = e0 * d;
        out[(size_t)n * 2 + 1] = e1 * d;
    }
}

// ---------------- launch -----------------------------------------------------
extern "C" void kernel_launch(void* const* d_in, const int* in_sizes, int n_in,
                              void* d_out, int out_size) {
    const float* feat = (const float*)d_in[0];
    const int*   ei   = (const int*)d_in[1];
    const float* W1l  = (const float*)d_in[2];
    const float* b1   = (const float*)d_in[3];
    const float* W1r  = (const float*)d_in[4];
    const float* W2l  = (const float*)d_in[5];
    const float* b2   = (const float*)d_in[6];
    const float* W2r  = (const float*)d_in[7];
    const float* Wfc  = (const float*)d_in[8];
    const float* bfc  = (const float*)d_in[9];
    float* out = (float*)d_out;

    float *p_y;
    cudaGetSymbolAddress((void**)&p_y, g_y);
    __nv_bfloat16 *p_wh1, *p_wl1, *p_wh2, *p_wl2;
    cudaGetSymbolAddress((void**)&p_wh1, g_wh1);
    cudaGetSymbolAddress((void**)&p_wl1, g_wl1);
    cudaGetSymbolAddress((void**)&p_wh2, g_wh2);
    cudaGetSymbolAddress((void**)&p_wl2, g_wl2);

    const int SMEM = 2 * 4 * 128 * 40 * 2;  // 81920 B
    cudaFuncSetAttribute(gs_gemm_pipe<1>, cudaFuncAttributeMaxDynamicSharedMemorySize, SMEM);
    cudaFuncSetAttribute(gs_gemm_pipe<2>, cudaFuncAttributeMaxDynamicSharedMemorySize, SMEM);

    // CSR build
    gs_zero_deg<<<(NN + 255) / 256, 256>>>();
    gs_hist<<<(NE + 255) / 256, 256>>>(ei);
    gs_scanA<<<49, 1024>>>();
    gs_scanB<<<1, 64>>>();
    gs_scanC<<<(NN + 255) / 256, 256>>>();
    gs_fill<<<(NE + 255) / 256, 256>>>(ei);

    // layer 1
    gs_gather1<<<(NN * 32 + 255) / 256, 256>>>(feat);
    gs_wsplit<<<(131072 + 255) / 256, 256>>>(W1l, W1r, W2l, W2r);
    {
        dim3 grid((NN + 127) / 128, 2);
        gs_gemm_pipe<1><<<grid, 256, SMEM>>>(p_wh1, p_wl1, b1, p_y);
    }
    gs_norm_relu_split<<<(NN * 32 + 255) / 256, 256>>>();

    // layer 2
    {
        dim3 grid((NN + 127) / 128, 2);
        gs_gemm_pipe<2><<<grid, 256, SMEM>>>(p_wh2, p_wl2, nullptr, p_y);
    }
    gs_gather2<<<(NN * 32 + 255) / 256, 256>>>();
    gs_final_kernel<<<(NN * 32 + 255) / 256, 256>>>(b2, Wfc, bfc, out);
}

// round 4
// speedup vs baseline: 2.7114x; 1.0587x over previous
#include <cuda_runtime.h>
#include <cuda_bf16.h>
#include <cstdint>

#define NN 50000
#define NE 600000
#define NPAD 50176   // NN padded past grid coverage (50048); pad rows stay zero

// ---------------- device-global scratch ------------------------------------
__device__ int   g_deg[NN];
__device__ int   g_off[NN];
__device__ int   g_pos[NN];
__device__ int   g_ctr;
__device__ int   g_esrc[NE];
__device__ float g_inv[NN];
__device__ __nv_bfloat16 g_ah[NPAD * 256];
__device__ __nv_bfloat16 g_al[NPAD * 256];
__device__ __nv_bfloat16 g_wh1[256 * 256], g_wl1[256 * 256];
__device__ __nv_bfloat16 g_wh2[256 * 256], g_wl2[256 * 256];
__device__ float g_y[NN * 256];

// ---------------- small helpers --------------------------------------------
__device__ __forceinline__ uint32_t smem_u32(const void* p) {
    return (uint32_t)__cvta_generic_to_shared(p);
}
__device__ __forceinline__ void cp16(uint32_t dst, const void* src) {
    asm volatile("cp.async.cg.shared.global [%0], [%1], 16;" :: "r"(dst), "l"(src));
}
__device__ __forceinline__ void cp_commit() {
    asm volatile("cp.async.commit_group;");
}
template <int N> __device__ __forceinline__ void cp_wait() {
    asm volatile("cp.async.wait_group %0;" :: "n"(N));
}
__device__ __forceinline__ void ldm_x4(uint32_t* r, uint32_t addr) {
    asm volatile("ldmatrix.sync.aligned.m8n8.x4.shared.b16 {%0,%1,%2,%3}, [%4];"
                 : "=r"(r[0]), "=r"(r[1]), "=r"(r[2]), "=r"(r[3]) : "r"(addr));
}
__device__ __forceinline__ void mma_bf16(float* c, const uint32_t* a, const uint32_t* b) {
    asm volatile("mma.sync.aligned.m16n8k16.row.col.f32.bf16.bf16.f32 "
                 "{%0,%1,%2,%3}, {%4,%5,%6,%7}, {%8,%9}, {%0,%1,%2,%3};"
                 : "+f"(c[0]), "+f"(c[1]), "+f"(c[2]), "+f"(c[3])
                 : "r"(a[0]), "r"(a[1]), "r"(a[2]), "r"(a[3]), "r"(b[0]), "r"(b[1]));
}
__device__ __forceinline__ void bf16_split(float x, __nv_bfloat16& h, __nv_bfloat16& l) {
    h = __float2bfloat16(x);
    l = __float2bfloat16(x - __bfloat162float(h));
}

// ---------------- CSR build (scanless) ---------------------------------------
__global__ void gs_zero_deg() {
    int i = blockIdx.x * blockDim.x + threadIdx.x;
    if (i < NN) g_deg[i] = 0;
    if (i == 0) g_ctr = 0;
}
__global__ void gs_hist(const int* __restrict__ ei) {
    int e = blockIdx.x * blockDim.x + threadIdx.x;
    if (e < NE) atomicAdd(&g_deg[ei[NE + e]], 1);
}
// warp-aggregated offset assignment (segment order is arbitrary; gather only
// needs disjoint [off, off+deg) ranges)
__global__ void gs_offs() {
    int n = blockIdx.x * blockDim.x + threadIdx.x;
    int lane = threadIdx.x & 31;
    int d = (n < NN) ? g_deg[n] : 0;
    int s = d;
    #pragma unroll
    for (int o = 1; o < 32; o <<= 1) {
        int t = __shfl_up_sync(0xffffffffu, s, o);
        if (lane >= o) s += t;
    }
    int tot = __shfl_sync(0xffffffffu, s, 31);
    int base = 0;
    if (lane == 0) base = atomicAdd(&g_ctr, tot);
    base = __shfl_sync(0xffffffffu, base, 0);
    if (n < NN) {
        int o = base + s - d;
        g_off[n] = o;
        g_pos[n] = o;
    }
}
__global__ void gs_fill(const int* __restrict__ ei) {
    int e = blockIdx.x * blockDim.x + threadIdx.x;
    if (e >= NE) return;
    int s = ei[e], d = ei[NE + e];
    int p = atomicAdd(&g_pos[d], 1);
    g_esrc[p] = s;
}

// ---------------- gather 1: mean(feat[nbrs]) + own feat -> split bf16 A ------
__global__ void gs_gather1(const float* __restrict__ feat) {
    int t = blockIdx.x * blockDim.x + threadIdx.x;
    int n = t >> 5;
    if (n >= NN) return;
    int lane = t & 31;
    int start = g_off[n], deg = g_deg[n];

    float4 acc = make_float4(0.f, 0.f, 0.f, 0.f);
    int i = 0;
    for (; i + 2 <= deg; i += 2) {
        int s0 = g_esrc[start + i];
        int s1 = g_esrc[start + i + 1];
        float4 v0 = *(const float4*)(feat + (size_t)s0 * 128 + lane * 4);
        float4 v1 = *(const float4*)(feat + (size_t)s1 * 128 + lane * 4);
        acc.x += v0.x + v1.x; acc.y += v0.y + v1.y;
        acc.z += v0.z + v1.z; acc.w += v0.w + v1.w;
    }
    if (i < deg) {
        int s0 = g_esrc[start + i];
        float4 v0 = *(const float4*)(feat + (size_t)s0 * 128 + lane * 4);
        acc.x += v0.x; acc.y += v0.y; acc.z += v0.z; acc.w += v0.w;
    }
    float inv = 1.0f / fmaxf((float)deg, 1.0f);
    if (lane == 0) g_inv[n] = inv;
    acc.x *= inv; acc.y *= inv; acc.z *= inv; acc.w *= inv;

    __nv_bfloat16 h0, l0, h1, l1, h2, l2, h3, l3;
    bf16_split(acc.x, h0, l0); bf16_split(acc.y, h1, l1);
    bf16_split(acc.z, h2, l2); bf16_split(acc.w, h3, l3);
    size_t base = (size_t)n * 256 + lane * 4;
    ((__nv_bfloat162*)(g_ah + base))[0] = __nv_bfloat162(h0, h1);
    ((__nv_bfloat162*)(g_ah + base))[1] = __nv_bfloat162(h2, h3);
    ((__nv_bfloat162*)(g_al + base))[0] = __nv_bfloat162(l0, l1);
    ((__nv_bfloat162*)(g_al + base))[1] = __nv_bfloat162(l2, l3);

    float4 f = *(const float4*)(feat + (size_t)n * 128 + lane * 4);
    bf16_split(f.x, h0, l0); bf16_split(f.y, h1, l1);
    bf16_split(f.z, h2, l2); bf16_split(f.w, h3, l3);
    size_t base2 = (size_t)n * 256 + 128 + lane * 4;
    ((__nv_bfloat162*)(g_ah + base2))[0] = __nv_bfloat162(h0, h1);
    ((__nv_bfloat162*)(g_ah + base2))[1] = __nv_bfloat162(h2, h3);
    ((__nv_bfloat162*)(g_al + base2))[0] = __nv_bfloat162(l0, l1);
    ((__nv_bfloat162*)(g_al + base2))[1] = __nv_bfloat162(l2, l3);
}

// ---------------- weight split: build concat layouts, bf16 hi/lo -------------
__global__ void gs_wsplit(const float* __restrict__ W1l, const float* __restrict__ W1r,
                          const float* __restrict__ W2l, const float* __restrict__ W2r) {
    int i = blockIdx.x * blockDim.x + threadIdx.x;
    if (i < 65536) {
        int n = i >> 8, k = i & 255;
        float w = (k < 128) ? W1l[n * 128 + k] : W1r[n * 128 + (k - 128)];
        __nv_bfloat16 h, l;
        bf16_split(w, h, l);
        g_wh1[i] = h; g_wl1[i] = l;
    } else if (i < 131072) {
        int j = i - 65536;
        int n = j >> 8, k = j & 255;
        float w = (n < 128) ? W2l[n * 256 + k] : W2r[(n - 128) * 256 + k];
        __nv_bfloat16 h, l;
        bf16_split(w, h, l);
        g_wh2[j] = h; g_wl2[j] = l;
    }
}

// ---------------- pipelined bf16x3 GEMM: C[NN,256] = A @ W^T (+bias) --------
// Single __syncthreads per k-tile: wait -> sync -> issue(next) -> compute.
template <int MODE>
__global__ __launch_bounds__(256, 2)
void gs_gemm_pipe(const __nv_bfloat16* __restrict__ Wh,
                  const __nv_bfloat16* __restrict__ Wl,
                  const float* __restrict__ bias,
                  float* __restrict__ C) {
    constexpr int STR = 40;           // bf16 per smem row (32 + 8 pad)
    constexpr int TSZ = 128 * STR;    // elems per tile
    extern __shared__ __nv_bfloat16 sm[];

    const int tid  = threadIdx.x;
    const int lane = tid & 31;
    const int warp = tid >> 5;
    const int wm   = warp >> 1;       // 0..3 -> m offset wm*32
    const int wn   = warp & 1;        // 0..1 -> n offset wn*64
    const int m0   = blockIdx.x * 128;
    const int n0   = blockIdx.y * 128;

    float c[2][8][4];
    #pragma unroll
    for (int a = 0; a < 2; ++a)
        #pragma unroll
        for (int b = 0; b < 8; ++b)
            #pragma unroll
            for (int k = 0; k < 4; ++k) c[a][b][k] = 0.f;

    auto issue_load = [&](int kt, int st) {
        const int k0 = kt * 32;
        __nv_bfloat16* base = sm + st * 4 * TSZ;
        #pragma unroll
        for (int l = 0; l < 2; ++l) {
            int idx = tid + l * 256;   // 0..511
            int r   = idx >> 2;        // 0..127
            int cq  = (idx & 3) * 8;   // bf16 col offset 0,8,16,24
            uint32_t ds = smem_u32(base + r * STR + cq);
            cp16(ds,             g_ah + (size_t)(m0 + r) * 256 + k0 + cq);
            cp16(ds + TSZ * 2,   g_al + (size_t)(m0 + r) * 256 + k0 + cq);
            cp16(ds + TSZ * 4,   Wh   + (size_t)(n0 + r) * 256 + k0 + cq);
            cp16(ds + TSZ * 6,   Wl   + (size_t)(n0 + r) * 256 + k0 + cq);
        }
        cp_commit();
    };

    issue_load(0, 0);

    for (int kt = 0; kt < 8; ++kt) {
        const int st = kt & 1;
        cp_wait<0>();
        __syncthreads();               // publishes stage st; retires readers of st^1
        if (kt + 1 < 8) issue_load(kt + 1, st ^ 1);

        const __nv_bfloat16* Ahs = sm + st * 4 * TSZ;
        const __nv_bfloat16* Als = Ahs + TSZ;
        const __nv_bfloat16* Bhs = Ahs + 2 * TSZ;
        const __nv_bfloat16* Bls = Ahs + 3 * TSZ;

        #pragma unroll
        for (int ks = 0; ks < 2; ++ks) {
            uint32_t ah[2][4], al[2][4];
            #pragma unroll
            for (int mi = 0; mi < 2; ++mi) {
                int r  = wm * 32 + mi * 16 + (lane & 15);
                int cc = ks * 16 + (lane >> 4) * 8;
                ldm_x4(ah[mi], smem_u32(Ahs + r * STR + cc));
                ldm_x4(al[mi], smem_u32(Als + r * STR + cc));
            }
            int mq = lane >> 3, ri = lane & 7;
            #pragma unroll
            for (int nip = 0; nip < 4; ++nip) {
                int row = wn * 64 + nip * 16 + (mq >> 1) * 8 + ri;
                int col = ks * 16 + (mq & 1) * 8;
                uint32_t bh4[4], bl4[4];
                ldm_x4(bh4, smem_u32(Bhs + row * STR + col));
                ldm_x4(bl4, smem_u32(Bls + row * STR + col));
                #pragma unroll
                for (int mi = 0; mi < 2; ++mi) {
                    mma_bf16(c[mi][2 * nip + 0], ah[mi], &bh4[0]);
                    mma_bf16(c[mi][2 * nip + 0], ah[mi], &bl4[0]);
                    mma_bf16(c[mi][2 * nip + 0], al[mi], &bh4[0]);
                    mma_bf16(c[mi][2 * nip + 1], ah[mi], &bh4[2]);
                    mma_bf16(c[mi][2 * nip + 1], ah[mi], &bl4[2]);
                    mma_bf16(c[mi][2 * nip + 1], al[mi], &bh4[2]);
                }
            }
        }
    }

    // ---- epilogue ------------------------------------------------------------
    #pragma unroll
    for (int mi = 0; mi < 2; ++mi) {
        int row = m0 + wm * 32 + mi * 16 + (lane >> 2);
        #pragma unroll
        for (int ni = 0; ni < 8; ++ni) {
            int col = n0 + wn * 64 + ni * 8 + (lane & 3) * 2;
            float2 v0 = make_float2(c[mi][ni][0], c[mi][ni][1]);
            float2 v1 = make_float2(c[mi][ni][2], c[mi][ni][3]);
            if (MODE == 1) {
                float b0 = bias[col], b1 = bias[col + 1];
                v0.x += b0; v0.y += b1;
                v1.x += b0; v1.y += b1;
            }
            if (row < NN)     *(float2*)(C + (size_t)row * 256 + col)       = v0;
            if (row + 8 < NN) *(float2*)(C + (size_t)(row + 8) * 256 + col) = v1;
        }
    }
}

// ---------------- layer-1 epilogue: normalize + relu -> split bf16 ----------
__global__ void gs_norm_relu_split() {
    int t = blockIdx.x * blockDim.x + threadIdx.x;
    int n = t >> 5;
    if (n >= NN) return;
    int lane = t & 31;
    const float* row = g_y + (size_t)n * 256;
    float4 v0 = *(const float4*)(row + lane * 4);
    float4 v1 = *(const float4*)(row + 128 + lane * 4);
    float s = v0.x * v0.x + v0.y * v0.y + v0.z * v0.z + v0.w * v0.w
            + v1.x * v1.x + v1.y * v1.y + v1.z * v1.z + v1.w * v1.w;
    #pragma unroll
    for (int o = 16; o > 0; o >>= 1) s += __shfl_xor_sync(0xffffffffu, s, o);
    float scale = 1.0f / fmaxf(sqrtf(s), 1e-12f);

    float r0 = fmaxf(v0.x * scale, 0.f), r1 = fmaxf(v0.y * scale, 0.f);
    float r2 = fmaxf(v0.z * scale, 0.f), r3 = fmaxf(v0.w * scale, 0.f);
    float r4 = fmaxf(v1.x * scale, 0.f), r5 = fmaxf(v1.y * scale, 0.f);
    float r6 = fmaxf(v1.z * scale, 0.f), r7 = fmaxf(v1.w * scale, 0.f);

    __nv_bfloat16 h0, l0, h1, l1, h2, l2, h3, l3;
    size_t base = (size_t)n * 256 + lane * 4;
    bf16_split(r0, h0, l0); bf16_split(r1, h1, l1);
    bf16_split(r2, h2, l2); bf16_split(r3, h3, l3);
    ((__nv_bfloat162*)(g_ah + base))[0] = __nv_bfloat162(h0, h1);
    ((__nv_bfloat162*)(g_ah + base))[1] = __nv_bfloat162(h2, h3);
    ((__nv_bfloat162*)(g_al + base))[0] = __nv_bfloat162(l0, l1);
    ((__nv_bfloat162*)(g_al + base))[1] = __nv_bfloat162(l2, l3);

    size_t base2 = base + 128;
    bf16_split(r4, h0, l0); bf16_split(r5, h1, l1);
    bf16_split(r6, h2, l2); bf16_split(r7, h3, l3);
    ((__nv_bfloat162*)(g_ah + base2))[0] = __nv_bfloat162(h0, h1);
    ((__nv_bfloat162*)(g_ah + base2))[1] = __nv_bfloat162(h2, h3);
    ((__nv_bfloat162*)(g_al + base2))[0] = __nv_bfloat162(l0, l1);
    ((__nv_bfloat162*)(g_al + base2))[1] = __nv_bfloat162(l2, l3);
}

// ---------------- fused gather2 + final head --------------------------------
// mean(yl[nbrs]) + yr + b2 -> L2 normalize -> fc -> softmax -> out
__global__ void gs_gather2_final(const float* __restrict__ b2,
                                 const float* __restrict__ Wfc,
                                 const float* __restrict__ bfc,
                                 float* __restrict__ out) {
    int t = blockIdx.x * blockDim.x + threadIdx.x;
    int n = t >> 5;
    if (n >= NN) return;
    int lane = t & 31;
    int start = g_off[n], deg = g_deg[n];

    float4 acc = make_float4(0.f, 0.f, 0.f, 0.f);
    int i = 0;
    for (; i + 2 <= deg; i += 2) {
        int s0 = g_esrc[start + i];
        int s1 = g_esrc[start + i + 1];
        float4 v0 = *(const float4*)(g_y + (size_t)s0 * 256 + lane * 4);
        float4 v1 = *(const float4*)(g_y + (size_t)s1 * 256 + lane * 4);
        acc.x += v0.x + v1.x; acc.y += v0.y + v1.y;
        acc.z += v0.z + v1.z; acc.w += v0.w + v1.w;
    }
    if (i < deg) {
        int s0 = g_esrc[start + i];
        float4 v0 = *(const float4*)(g_y + (size_t)s0 * 256 + lane * 4);
        acc.x += v0.x; acc.y += v0.y; acc.z += v0.z; acc.w += v0.w;
    }
    float inv = g_inv[n];

    float4 r  = *(const float4*)(g_y + (size_t)n * 256 + 128 + lane * 4); // yr
    float4 bb = *(const float4*)(b2 + lane * 4);
    float4 v;
    v.x = acc.x * inv + r.x + bb.x;
    v.y = acc.y * inv + r.y + bb.y;
    v.z = acc.z * inv + r.z + bb.z;
    v.w = acc.w * inv + r.w + bb.w;

    float s = v.x * v.x + v.y * v.y + v.z * v.z + v.w * v.w;
    #pragma unroll
    for (int o = 16; o > 0; o >>= 1) s += __shfl_xor_sync(0xffffffffu, s, o);
    float scale = 1.0f / fmaxf(sqrtf(s), 1e-12f);
    v.x *= scale; v.y *= scale; v.z *= scale; v.w *= scale;

    float4 w0 = *(const float4*)(Wfc + lane * 4);
    float4 w1 = *(const float4*)(Wfc + 128 + lane * 4);
    float l0 = v.x * w0.x + v.y * w0.y + v.z * w0.z + v.w * w0.w;
    float l1 = v.x * w1.x + v.y * w1.y + v.z * w1.z + v.w * w1.w;
    #pragma unroll
    for (int o = 16; o > 0; o >>= 1) {
        l0 += __shfl_xor_sync(0xffffffffu, l0, o);
        l1 += __shfl_xor_sync(0xffffffffu, l1, o);
    }
    if (lane == 0) {
        l0 += bfc[0]; l1 += bfc[1];
        float m  = fmaxf(l0, l1);
        float e0 = expf(l0 - m), e1 = expf(l1 - m);
        float d  = 1.0f / (e0 + e1);
        out[(size_t)n * 2 + 0] = e0 * d;
        out[(size_t)n * 2 + 1] = e1 * d;
    }
}

// ---------------- launch -----------------------------------------------------
extern "C" void kernel_launch(void* const* d_in, const int* in_sizes, int n_in,
                              void* d_out, int out_size) {
    const float* feat = (const float*)d_in[0];
    const int*   ei   = (const int*)d_in[1];
    const float* W1l  = (const float*)d_in[2];
    const float* b1   = (const float*)d_in[3];
    const float* W1r  = (const float*)d_in[4];
    const float* W2l  = (const float*)d_in[5];
    const float* b2   = (const float*)d_in[6];
    const float* W2r  = (const float*)d_in[7];
    const float* Wfc  = (const float*)d_in[8];
    const float* bfc  = (const float*)d_in[9];
    float* out = (float*)d_out;

    float* p_y;
    cudaGetSymbolAddress((void**)&p_y, g_y);
    __nv_bfloat16 *p_wh1, *p_wl1, *p_wh2, *p_wl2;
    cudaGetSymbolAddress((void**)&p_wh1, g_wh1);
    cudaGetSymbolAddress((void**)&p_wl1, g_wl1);
    cudaGetSymbolAddress((void**)&p_wh2, g_wh2);
    cudaGetSymbolAddress((void**)&p_wl2, g_wl2);

    const int SMEM = 2 * 4 * 128 * 40 * 2;  // 81920 B
    cudaFuncSetAttribute(gs_gemm_pipe<1>, cudaFuncAttributeMaxDynamicSharedMemorySize, SMEM);
    cudaFuncSetAttribute(gs_gemm_pipe<2>, cudaFuncAttributeMaxDynamicSharedMemorySize, SMEM);

    // CSR build (4 launches)
    gs_zero_deg<<<(NN + 255) / 256, 256>>>();
    gs_hist<<<(NE + 255) / 256, 256>>>(ei);
    gs_offs<<<(NN + 255) / 256, 256>>>();
    gs_fill<<<(NE + 255) / 256, 256>>>(ei);

    // layer 1
    gs_gather1<<<(NN * 32 + 255) / 256, 256>>>(feat);
    gs_wsplit<<<(131072 + 255) / 256, 256>>>(W1l, W1r, W2l, W2r);
    {
        dim3 grid((NN + 127) / 128, 2);
        gs_gemm_pipe<1><<<grid, 256, SMEM>>>(p_wh1, p_wl1, b1, p_y);
    }
    gs_norm_relu_split<<<(NN * 32 + 255) / 256, 256>>>();

    // layer 2
    {
        dim3 grid((NN + 127) / 128, 2);
        gs_gemm_pipe<2><<<grid, 256, SMEM>>>(p_wh2, p_wl2, nullptr, p_y);
    }
    gs_gather2_final<<<(NN * 32 + 255) / 256, 256>>>(b2, Wfc, bfc, out);
}